// round 8
// baseline (speedup 1.0000x reference)
#include <cuda_runtime.h>

#define NN 100000
#define GG 2048
#define CAP 64
#define AGG_WARPS 8

// ---------------- device scratch (no allocations allowed) ----------------
__device__ int   g_ctr[NN];                 // per-dst edge counter (== degree after build)
__device__ int   g_csr[(size_t)NN * CAP];   // src ids per dst row (fixed stride)
__device__ float g_h  [(size_t)NN * 32];    // current layer h = xW
__device__ float g_out[(size_t)NN * 32];    // layer output / next layer input
__device__ float g_es [NN];
__device__ float g_ed [NN];

// ---------------- CSR build ----------------
__global__ void k_init()
{
    int i = blockIdx.x * blockDim.x + threadIdx.x;
    if (i < NN) {
        g_ctr[i] = 1;                // self loop occupies slot 0
        g_csr[(size_t)i * CAP] = i;
    }
}

__global__ void k_scatter(const int* __restrict__ src,
                          const int* __restrict__ dst, int E)
{
    int e = blockIdx.x * blockDim.x + threadIdx.x;
    if (e < E) {
        int d = dst[e];
        int s = src[e];
        if ((unsigned)d < NN && (unsigned)s < NN) {
            int pos = atomicAdd(&g_ctr[d], 1);
            if (pos < CAP) g_csr[(size_t)d * CAP + pos] = s;
        }
    }
}

// ---------------- GEMM: g_h[N,32] = X[N,K] @ W[K,32], fused es/ed ----------------
template <int K, bool USE_GOUT>
__global__ void k_gemm(const float* __restrict__ X, const float* __restrict__ W,
                       const float* __restrict__ a_s, const float* __restrict__ a_d)
{
    __shared__ float xs[32][260];   // transposed x chunk: xs[kk][node_local]
    __shared__ float ws[32][32];    // W chunk

    const float* __restrict__ src = USE_GOUT ? (const float*)g_out : X;

    int tid  = threadIdx.x;
    int lane = tid & 31;
    int warp = tid >> 5;
    int k4   = lane & 7;
    int ngl  = lane >> 3;
    int nodeBlock = blockIdx.x * 256;
    int nodeLoc0  = warp * 32 + ngl * 8;   // local base of my 8 nodes

    float acc[8][4];
#pragma unroll
    for (int m = 0; m < 8; m++)
#pragma unroll
        for (int j = 0; j < 4; j++) acc[m][j] = 0.f;

    for (int c = 0; c < K / 32; c++) {
        int node = nodeBlock + tid;
        float4 tmp[8];
        if (node < NN) {
            const float4* xr = reinterpret_cast<const float4*>(src + (size_t)node * K + c * 32);
#pragma unroll
            for (int q = 0; q < 8; q++) tmp[q] = xr[q];
        } else {
#pragma unroll
            for (int q = 0; q < 8; q++) tmp[q] = make_float4(0.f, 0.f, 0.f, 0.f);
        }
#pragma unroll
        for (int q = 0; q < 8; q++) {
            xs[q * 4 + 0][tid] = tmp[q].x;
            xs[q * 4 + 1][tid] = tmp[q].y;
            xs[q * 4 + 2][tid] = tmp[q].z;
            xs[q * 4 + 3][tid] = tmp[q].w;
        }
        for (int i = tid; i < 1024; i += 256) ws[i >> 5][i & 31] = W[c * 1024 + i];
        __syncthreads();

#pragma unroll 8
        for (int kk = 0; kk < 32; kk++) {
            float4 wv = *reinterpret_cast<const float4*>(&ws[kk][k4 * 4]);
            float4 xa = *reinterpret_cast<const float4*>(&xs[kk][nodeLoc0]);
            float4 xb = *reinterpret_cast<const float4*>(&xs[kk][nodeLoc0 + 4]);
            float xv[8] = {xa.x, xa.y, xa.z, xa.w, xb.x, xb.y, xb.z, xb.w};
#pragma unroll
            for (int m = 0; m < 8; m++) {
                acc[m][0] += xv[m] * wv.x;
                acc[m][1] += xv[m] * wv.y;
                acc[m][2] += xv[m] * wv.z;
                acc[m][3] += xv[m] * wv.w;
            }
        }
        __syncthreads();
    }

    float4 asv = reinterpret_cast<const float4*>(a_s)[k4];
    float4 adv = reinterpret_cast<const float4*>(a_d)[k4];
#pragma unroll
    for (int m = 0; m < 8; m++) {
        int node = nodeBlock + nodeLoc0 + m;
        float sp = acc[m][0] * asv.x + acc[m][1] * asv.y + acc[m][2] * asv.z + acc[m][3] * asv.w;
        float dp = acc[m][0] * adv.x + acc[m][1] * adv.y + acc[m][2] * adv.z + acc[m][3] * adv.w;
#pragma unroll
        for (int off = 4; off > 0; off >>= 1) {
            sp += __shfl_xor_sync(0xffffffffu, sp, off);
            dp += __shfl_xor_sync(0xffffffffu, dp, off);
        }
        if (node < NN) {
            reinterpret_cast<float4*>(g_h + (size_t)node * 32)[k4] =
                make_float4(acc[m][0], acc[m][1], acc[m][2], acc[m][3]);
            if (k4 == 0) { g_es[node] = sp; g_ed[node] = dp; }
        }
    }
}

// ---------------- edge softmax + aggregation ----------------
// 4 nodes per warp, 8 lanes per node (lane = g*8 + q), float4 of features per lane.
// Phase 1 (lane-parallel): weights for entries k*8+q into SMEM; group-reduce denom.
// Phase 2: LDS-broadcast (s,w) + independent LDG.128 gathers, 2 accumulators.
__global__ void __launch_bounds__(256, 5) k_agg(const float* __restrict__ bias)
{
    __shared__ int   ss[AGG_WARPS][4][CAP];
    __shared__ float ww[AGG_WARPS][4][CAP];

    const unsigned FULL = 0xffffffffu;
    int wid  = threadIdx.x >> 5;
    int lane = threadIdx.x & 31;
    int g = lane >> 3;          // node group within warp
    int q = lane & 7;           // feature quad within node

    int warpGlobal = blockIdx.x * AGG_WARPS + wid;
    int node = warpGlobal * 4 + g;
    bool valid = node < NN;

    int deg = 0;
    float edi = 0.f;
    if (valid) {
        deg = g_ctr[node];
        if (deg > CAP) deg = CAP;
        edi = g_ed[node];
    }
    const int* row = g_csr + (size_t)(valid ? node : 0) * CAP;

    // ---- phase 1: per-lane edge weights into smem ----
    float den = 0.f;
#pragma unroll
    for (int k = 0; k < 8; k++) {
        int e = k * 8 + q;
        int s = (e < deg) ? row[e] : 0;
        float w = 0.f;
        if (e < deg) {
            float ee = g_es[s] + edi;
            ee = (ee > 0.f) ? ee : 0.2f * ee;
            w = __expf(ee);
        }
        ss[wid][g][e] = s;
        ww[wid][g][e] = w;
        den += w;
    }
#pragma unroll
    for (int off = 4; off > 0; off >>= 1)
        den += __shfl_xor_sync(FULL, den, off);

    int degMax = deg;
#pragma unroll
    for (int off = 16; off > 0; off >>= 1) {
        int o = __shfl_xor_sync(FULL, degMax, off);
        degMax = o > degMax ? o : degMax;
    }
    __syncwarp();

    // ---- phase 2: gather; chunks of 8 edges, independent loads ----
    float4 acc0 = make_float4(0.f, 0.f, 0.f, 0.f);
    float4 acc1 = make_float4(0.f, 0.f, 0.f, 0.f);
    const int*   srow = ss[wid][g];
    const float* wrow = ww[wid][g];
    for (int k = 0; k * 8 < degMax; k++) {
        int   sv[8];
        float wv[8];
#pragma unroll
        for (int j = 0; j < 8; j++) {
            sv[j] = srow[k * 8 + j];
            wv[j] = wrow[k * 8 + j];
        }
#pragma unroll
        for (int j = 0; j < 8; j += 2) {
            float4 h0 = *reinterpret_cast<const float4*>(g_h + (size_t)sv[j] * 32 + q * 4);
            float4 h1 = *reinterpret_cast<const float4*>(g_h + (size_t)sv[j + 1] * 32 + q * 4);
            acc0.x += wv[j] * h0.x;  acc0.y += wv[j] * h0.y;
            acc0.z += wv[j] * h0.z;  acc0.w += wv[j] * h0.w;
            acc1.x += wv[j + 1] * h1.x;  acc1.y += wv[j + 1] * h1.y;
            acc1.z += wv[j + 1] * h1.z;  acc1.w += wv[j + 1] * h1.w;
        }
    }

    if (valid) {
        float inv = 1.f / den;
        float4 b4 = reinterpret_cast<const float4*>(bias)[q];
        float4 o;
        o.x = (acc0.x + acc1.x) * inv + b4.x;
        o.y = (acc0.y + acc1.y) * inv + b4.y;
        o.z = (acc0.z + acc1.z) * inv + b4.z;
        o.w = (acc0.w + acc1.w) * inv + b4.w;
        reinterpret_cast<float4*>(g_out + (size_t)node * 32)[q] = o;
    }
}

// ---------------- global mean pool: batch is SORTED -> segmented reduction ----------
__global__ void k_pool(const int* __restrict__ batch, float* __restrict__ out)
{
    int g    = (blockIdx.x * blockDim.x + threadIdx.x) >> 5;
    int lane = threadIdx.x & 31;
    if (g >= GG) return;

    int lo = 0, hi = NN;
    while (lo < hi) { int mid = (lo + hi) >> 1; if (batch[mid] < g) lo = mid + 1; else hi = mid; }
    int start = lo;
    hi = NN;
    while (lo < hi) { int mid = (lo + hi) >> 1; if (batch[mid] < g + 1) lo = mid + 1; else hi = mid; }
    int end = lo;

    float a0 = 0.f, a1 = 0.f, a2 = 0.f, a3 = 0.f;
    int n = start;
    for (; n + 4 <= end; n += 4) {
        a0 += g_out[(size_t)(n + 0) * 32 + lane];
        a1 += g_out[(size_t)(n + 1) * 32 + lane];
        a2 += g_out[(size_t)(n + 2) * 32 + lane];
        a3 += g_out[(size_t)(n + 3) * 32 + lane];
    }
    for (; n < end; n++) a0 += g_out[(size_t)n * 32 + lane];

    int cnt = end - start;
    out[(size_t)g * 32 + lane] = (a0 + a1 + a2 + a3) / (float)(cnt > 0 ? cnt : 1);
}

// ---------------- launch ----------------
extern "C" void kernel_launch(void* const* d_in, const int* in_sizes, int n_in,
                              void* d_out, int out_size)
{
    const float* x     = (const float*)d_in[0];
    const int*   ei    = (const int*)d_in[1];
    const int*   batch = (const int*)d_in[2];
    int E = in_sizes[1] / 2;

    const float *W[4], *as_[4], *ad_[4], *bs_[4];
    for (int l = 0; l < 4; l++) {
        W[l]   = (const float*)d_in[3 + 4 * l];
        as_[l] = (const float*)d_in[4 + 4 * l];
        ad_[l] = (const float*)d_in[5 + 4 * l];
        bs_[l] = (const float*)d_in[6 + 4 * l];
    }
    float* out = (float*)d_out;

    const int nodeBlocks = (NN + 255) / 256;                          // 391
    const int aggBlocks  = (NN + 4 * AGG_WARPS - 1) / (4 * AGG_WARPS); // 3125

    k_init<<<nodeBlocks, 256>>>();
    k_scatter<<<(E + 255) / 256, 256>>>(ei, ei + E, E);

    // layer 1 (K = 128, input = x)
    k_gemm<128, false><<<nodeBlocks, 256>>>(x, W[0], as_[0], ad_[0]);
    k_agg<<<aggBlocks, 256>>>(bs_[0]);

    // layers 2..4 (K = 32, input = g_out)
    for (int l = 1; l < 4; l++) {
        k_gemm<32, true><<<nodeBlocks, 256>>>(nullptr, W[l], as_[l], ad_[l]);
        k_agg<<<aggBlocks, 256>>>(bs_[l]);
    }

    k_pool<<<(GG * 32 + 255) / 256, 256>>>(batch, out);
}

// round 9
// speedup vs baseline: 1.1747x; 1.1747x over previous
#include <cuda_runtime.h>

#define NN 100000
#define GG 2048
#define CAP 64

// ---------------- device scratch (no allocations allowed) ----------------
__device__ int   g_ctr[NN];                 // per-dst edge counter (== degree after build)
__device__ int   g_csr[(size_t)NN * CAP];   // src ids per dst row (fixed stride)
__device__ float g_h  [(size_t)NN * 32];    // current layer h = xW
__device__ float g_out[(size_t)NN * 32];    // layer output / next layer input
__device__ float g_es [NN];
__device__ float g_ed [NN];

// ---------------- CSR build ----------------
__global__ void k_init()
{
    int i = blockIdx.x * blockDim.x + threadIdx.x;
    if (i < NN) {
        g_ctr[i] = 1;                // self loop occupies slot 0
        g_csr[(size_t)i * CAP] = i;
    }
}

__global__ void k_scatter(const int* __restrict__ src,
                          const int* __restrict__ dst, int E)
{
    int e = blockIdx.x * blockDim.x + threadIdx.x;
    if (e < E) {
        int d = dst[e];
        int s = src[e];
        if ((unsigned)d < NN && (unsigned)s < NN) {
            int pos = atomicAdd(&g_ctr[d], 1);
            if (pos < CAP) g_csr[(size_t)d * CAP + pos] = s;
        }
    }
}

// ---------------- GEMM: g_h[N,32] = X[N,K] @ W[K,32], fused es/ed ----------------
template <int K, bool USE_GOUT>
__global__ void k_gemm(const float* __restrict__ X, const float* __restrict__ W,
                       const float* __restrict__ a_s, const float* __restrict__ a_d)
{
    __shared__ float xs[32][260];   // transposed x chunk: xs[kk][node_local]
    __shared__ float ws[32][32];    // W chunk

    const float* __restrict__ src = USE_GOUT ? (const float*)g_out : X;

    int tid  = threadIdx.x;
    int lane = tid & 31;
    int warp = tid >> 5;
    int k4   = lane & 7;
    int ngl  = lane >> 3;
    int nodeBlock = blockIdx.x * 256;
    int nodeLoc0  = warp * 32 + ngl * 8;   // local base of my 8 nodes

    float acc[8][4];
#pragma unroll
    for (int m = 0; m < 8; m++)
#pragma unroll
        for (int j = 0; j < 4; j++) acc[m][j] = 0.f;

    for (int c = 0; c < K / 32; c++) {
        int node = nodeBlock + tid;
        float4 tmp[8];
        if (node < NN) {
            const float4* xr = reinterpret_cast<const float4*>(src + (size_t)node * K + c * 32);
#pragma unroll
            for (int q = 0; q < 8; q++) tmp[q] = xr[q];
        } else {
#pragma unroll
            for (int q = 0; q < 8; q++) tmp[q] = make_float4(0.f, 0.f, 0.f, 0.f);
        }
#pragma unroll
        for (int q = 0; q < 8; q++) {
            xs[q * 4 + 0][tid] = tmp[q].x;
            xs[q * 4 + 1][tid] = tmp[q].y;
            xs[q * 4 + 2][tid] = tmp[q].z;
            xs[q * 4 + 3][tid] = tmp[q].w;
        }
        for (int i = tid; i < 1024; i += 256) ws[i >> 5][i & 31] = W[c * 1024 + i];
        __syncthreads();

#pragma unroll 8
        for (int kk = 0; kk < 32; kk++) {
            float4 wv = *reinterpret_cast<const float4*>(&ws[kk][k4 * 4]);
            float4 xa = *reinterpret_cast<const float4*>(&xs[kk][nodeLoc0]);
            float4 xb = *reinterpret_cast<const float4*>(&xs[kk][nodeLoc0 + 4]);
            float xv[8] = {xa.x, xa.y, xa.z, xa.w, xb.x, xb.y, xb.z, xb.w};
#pragma unroll
            for (int m = 0; m < 8; m++) {
                acc[m][0] += xv[m] * wv.x;
                acc[m][1] += xv[m] * wv.y;
                acc[m][2] += xv[m] * wv.z;
                acc[m][3] += xv[m] * wv.w;
            }
        }
        __syncthreads();
    }

    float4 asv = reinterpret_cast<const float4*>(a_s)[k4];
    float4 adv = reinterpret_cast<const float4*>(a_d)[k4];
#pragma unroll
    for (int m = 0; m < 8; m++) {
        int node = nodeBlock + nodeLoc0 + m;
        float sp = acc[m][0] * asv.x + acc[m][1] * asv.y + acc[m][2] * asv.z + acc[m][3] * asv.w;
        float dp = acc[m][0] * adv.x + acc[m][1] * adv.y + acc[m][2] * adv.z + acc[m][3] * adv.w;
#pragma unroll
        for (int off = 4; off > 0; off >>= 1) {
            sp += __shfl_xor_sync(0xffffffffu, sp, off);
            dp += __shfl_xor_sync(0xffffffffu, dp, off);
        }
        if (node < NN) {
            reinterpret_cast<float4*>(g_h + (size_t)node * 32)[k4] =
                make_float4(acc[m][0], acc[m][1], acc[m][2], acc[m][3]);
            if (k4 == 0) { g_es[node] = sp; g_ed[node] = dp; }
        }
    }
}

// ---------------- edge softmax + aggregation (single-phase) ----------------
// 4 nodes per warp, 8 lanes per node (lane = g*8 + q), float4 of features per lane.
// All 8 lanes of a group read the same CSR int4 (broadcast) and the same es[s]
// (broadcast) -> every lane computes every edge weight locally, so the softmax
// denominator needs NO reduction. No smem, no shfl, no second pass.
__global__ void k_agg(const float* __restrict__ bias)
{
    int warpGlobal = (blockIdx.x * blockDim.x + threadIdx.x) >> 5;
    int lane = threadIdx.x & 31;
    int g = lane >> 3;          // node group within warp
    int q = lane & 7;           // feature quad within node

    int node = warpGlobal * 4 + g;
    bool valid = node < NN;

    int deg = 0;
    float edi = 0.f;
    if (valid) {
        deg = g_ctr[node];
        if (deg > CAP) deg = CAP;
        edi = g_ed[node];
    }
    const int4* row4 = reinterpret_cast<const int4*>(g_csr + (size_t)(valid ? node : 0) * CAP);

    float4 acc = make_float4(0.f, 0.f, 0.f, 0.f);
    float den = 0.f;

    for (int k = 0; k * 4 < deg; k++) {
        int4 s4 = row4[k];                       // 8 lanes same addr -> broadcast
        int sv[4] = {s4.x, s4.y, s4.z, s4.w};
#pragma unroll
        for (int j = 0; j < 4; j++) {
            int e = k * 4 + j;
            if (e < deg) {
                int s = sv[j];
                float ee = g_es[s] + edi;        // broadcast within group
                ee = (ee > 0.f) ? ee : 0.2f * ee;
                float w = __expf(ee);
                den += w;
                float4 hv = *reinterpret_cast<const float4*>(g_h + (size_t)s * 32 + q * 4);
                acc.x += w * hv.x;
                acc.y += w * hv.y;
                acc.z += w * hv.z;
                acc.w += w * hv.w;
            }
        }
    }

    if (valid) {
        float inv = 1.f / den;
        float4 b4 = reinterpret_cast<const float4*>(bias)[q];
        float4 o;
        o.x = acc.x * inv + b4.x;
        o.y = acc.y * inv + b4.y;
        o.z = acc.z * inv + b4.z;
        o.w = acc.w * inv + b4.w;
        reinterpret_cast<float4*>(g_out + (size_t)node * 32)[q] = o;
    }
}

// ---------------- global mean pool: batch is SORTED -> segmented reduction ----------
__global__ void k_pool(const int* __restrict__ batch, float* __restrict__ out)
{
    int g    = (blockIdx.x * blockDim.x + threadIdx.x) >> 5;
    int lane = threadIdx.x & 31;
    if (g >= GG) return;

    int lo = 0, hi = NN;
    while (lo < hi) { int mid = (lo + hi) >> 1; if (batch[mid] < g) lo = mid + 1; else hi = mid; }
    int start = lo;
    hi = NN;
    while (lo < hi) { int mid = (lo + hi) >> 1; if (batch[mid] < g + 1) lo = mid + 1; else hi = mid; }
    int end = lo;

    float a0 = 0.f, a1 = 0.f, a2 = 0.f, a3 = 0.f;
    int n = start;
    for (; n + 4 <= end; n += 4) {
        a0 += g_out[(size_t)(n + 0) * 32 + lane];
        a1 += g_out[(size_t)(n + 1) * 32 + lane];
        a2 += g_out[(size_t)(n + 2) * 32 + lane];
        a3 += g_out[(size_t)(n + 3) * 32 + lane];
    }
    for (; n < end; n++) a0 += g_out[(size_t)n * 32 + lane];

    int cnt = end - start;
    out[(size_t)g * 32 + lane] = (a0 + a1 + a2 + a3) / (float)(cnt > 0 ? cnt : 1);
}

// ---------------- launch ----------------
extern "C" void kernel_launch(void* const* d_in, const int* in_sizes, int n_in,
                              void* d_out, int out_size)
{
    const float* x     = (const float*)d_in[0];
    const int*   ei    = (const int*)d_in[1];
    const int*   batch = (const int*)d_in[2];
    int E = in_sizes[1] / 2;

    const float *W[4], *as_[4], *ad_[4], *bs_[4];
    for (int l = 0; l < 4; l++) {
        W[l]   = (const float*)d_in[3 + 4 * l];
        as_[l] = (const float*)d_in[4 + 4 * l];
        ad_[l] = (const float*)d_in[5 + 4 * l];
        bs_[l] = (const float*)d_in[6 + 4 * l];
    }
    float* out = (float*)d_out;

    const int nodeBlocks = (NN + 255) / 256;              // 391
    const int aggBlocks  = (NN + 4 * 8 - 1) / (4 * 8);    // 4 nodes/warp, 8 warps/block -> 3125

    k_init<<<nodeBlocks, 256>>>();
    k_scatter<<<(E + 255) / 256, 256>>>(ei, ei + E, E);

    // layer 1 (K = 128, input = x)
    k_gemm<128, false><<<nodeBlocks, 256>>>(x, W[0], as_[0], ad_[0]);
    k_agg<<<aggBlocks, 256>>>(bs_[0]);

    // layers 2..4 (K = 32, input = g_out)
    for (int l = 1; l < 4; l++) {
        k_gemm<32, true><<<nodeBlocks, 256>>>(nullptr, W[l], as_[l], ad_[l]);
        k_agg<<<aggBlocks, 256>>>(bs_[l]);
    }

    k_pool<<<(GG * 32 + 255) / 256, 256>>>(batch, out);
}